// round 17
// baseline (speedup 1.0000x reference)
#include <cuda_runtime.h>
#include <cuda_bf16.h>
#include <math.h>
#include <stdint.h>

#define L1V   16
#define NLM   136
#define BB    4
#define NPTS  8192
#define CIN   64
#define COUT  64
#define SLOPE 0.01f
#define SROWS 272          // 17 m-tiles of 16, exact
#define KPAD  320          // synthesis K padded (5 chunks of 64)

// ---------------- scratch (zero-initialized device globals) ----------------
__device__ float    g_S[BB][SROWS][CIN];       // re-zeroed by middle_kernel each pass
__device__ uint16_t g_Tt[BB][2][KPAD][COUT];   // bf16 [hi/lo][k][n]; pad rows stay 0 forever

__constant__ float c_inv[17] = {
    0.f, 1.f, 1.f/2.f, 1.f/3.f, 1.f/4.f, 1.f/5.f, 1.f/6.f, 1.f/7.f, 1.f/8.f,
    1.f/9.f, 1.f/10.f, 1.f/11.f, 1.f/12.f, 1.f/13.f, 1.f/14.f, 1.f/15.f, 1.f/16.f};

#define SWZ(o) ((o) ^ (((o) >> 3) & 0x70))

// ---------------- helpers ----------------
__device__ __forceinline__ uint32_t smem_u32(const void* p) {
    uint32_t a;
    asm("{ .reg .u64 t; cvta.to.shared.u64 t, %1; cvt.u32.u64 %0, t; }" : "=r"(a) : "l"(p));
    return a;
}
__device__ __forceinline__ void ldsm4(uint32_t* r, uint32_t addr) {
    asm volatile("ldmatrix.sync.aligned.m8n8.x4.shared.b16 {%0,%1,%2,%3}, [%4];"
        : "=r"(r[0]), "=r"(r[1]), "=r"(r[2]), "=r"(r[3]) : "r"(addr));
}
__device__ __forceinline__ void ldsm4t(uint32_t* r, uint32_t addr) {
    asm volatile("ldmatrix.sync.aligned.m8n8.x4.trans.shared.b16 {%0,%1,%2,%3}, [%4];"
        : "=r"(r[0]), "=r"(r[1]), "=r"(r[2]), "=r"(r[3]) : "r"(addr));
}
__device__ __forceinline__ void mma16816(float* d, const uint32_t* a, const uint32_t* b) {
    asm volatile(
        "mma.sync.aligned.m16n8k16.row.col.f32.bf16.bf16.f32 "
        "{%0,%1,%2,%3}, {%4,%5,%6,%7}, {%8,%9}, {%0,%1,%2,%3};"
        : "+f"(d[0]), "+f"(d[1]), "+f"(d[2]), "+f"(d[3])
        : "r"(a[0]), "r"(a[1]), "r"(a[2]), "r"(a[3]), "r"(b[0]), "r"(b[1]));
}
__device__ __forceinline__ uint32_t pack_bf2(float a, float b) {
    __nv_bfloat162 h = __floats2bfloat162_rn(a, b);      // low half = a
    return *(uint32_t*)&h;
}
__device__ __forceinline__ void split_bf(float g, __nv_bfloat16& hi, __nv_bfloat16& lo) {
    hi = __float2bfloat16_rn(g);
    lo = __float2bfloat16_rn(g - __bfloat162float(hi));
}
__device__ __forceinline__ uint32_t prmt7632(uint32_t a, uint32_t b) {
    uint32_t r; asm("prmt.b32 %0, %1, %2, 0x7632;" : "=r"(r) : "r"(a), "r"(b)); return r;
}
__device__ __forceinline__ float trunc_res(float f, uint32_t bits) {
    return f - __uint_as_float(bits & 0xFFFF0000u);
}

// ---------------- kernel 1: analysis ----------------
// S[row][ch] += sum_pt G^T[row][pt] * V[pt][ch].  CTA: 128 pts (2 chunks of 64),
// 544 threads = 17 warps x 16 rows x 64 ch.  Gen: 512 threads, m in {mg, 15-mg};
// A split uses trunc-hi + packed bf16x2 lo (same scheme as B, fewer gen ALU ops).
__global__ __launch_bounds__(544, 2)
void analysis_kernel(const float* __restrict__ theta, const float* __restrict__ phi,
                     const float* __restrict__ areas, const float* __restrict__ values)
{
    extern __shared__ __align__(1024) char sh[];
    char* Ah = sh;                 // 272*128 = 34816
    char* Al = sh + 34816;
    char* Bh = sh + 69632;         // 64*128 = 8192
    char* Bl = sh + 77824;         // total 86016
    const uint32_t AhU = smem_u32(Ah), AlU = smem_u32(Al);
    const uint32_t BhU = smem_u32(Bh), BlU = smem_u32(Bl);

    const int tid  = threadIdx.x;
    const int b    = blockIdx.y;
    const int n0   = blockIdx.x * 128;
    const int warp = tid >> 5, lane = tid & 31;

    float acc[8][4];
#pragma unroll
    for (int j = 0; j < 8; ++j)
#pragma unroll
        for (int q = 0; q < 4; ++q) acc[j][q] = 0.f;

    for (int c = 0; c < 2; ++c) {
        __syncthreads();                       // previous chunk's mma done

        if (tid < 512) {
            const int pt = tid & 63, mg = tid >> 6;    // mg 0..7
            const int gi = b * NPTS + n0 + c * 64 + pt;
            const float th = theta[gi], ph = phi[gi], ar = areas[gi];
            const float x = cosf(th);
            const float s = sqrtf(fmaxf(1.f - x * x, 0.f));
#pragma unroll
            for (int half = 0; half < 2; ++half) {
                const int m = half ? (15 - mg) : mg;
                float smv, cmv;
                sincosf((float)m * ph, &smv, &cmv);
                const float ca = cmv * ar, sa = smv * ar;
                float pmm = 1.f;
                for (int i = 1; i <= m; ++i) pmm *= -(2.f * i - 1.f) * s;
                int r = m * L1V - (m * (m - 1)) / 2;
                float pa = 0.f, pb = pmm;
                float f2 = 2.f * m + 1.f, fl = 2.f * m;
                for (int l = m; l < L1V; ++l) {
                    const float gc = pb * ca, gs = pb * sa;
                    const uint32_t gcb = __float_as_uint(gc);
                    const uint32_t gsb = __float_as_uint(gs);
                    const int oc = SWZ((2 * r) * 128 + pt * 2);
                    const int os = SWZ((2 * r + 1) * 128 + pt * 2);
                    // hi = bf16-trunc (top 16 bits), stored directly
                    *(uint16_t*)(Ah + oc) = (uint16_t)(gcb >> 16);
                    *(uint16_t*)(Ah + os) = (uint16_t)(gsb >> 16);
                    // lo pair converted with ONE cvt.rn.bf16x2
                    const uint32_t lp = pack_bf2(trunc_res(gc, gcb), trunc_res(gs, gsb));
                    *(uint16_t*)(Al + oc) = (uint16_t)lp;
                    *(uint16_t*)(Al + os) = (uint16_t)(lp >> 16);
                    const float pn = (f2 * x * pb - fl * pa) * c_inv[l + 1 - m];
                    pa = pb; pb = pn; f2 += 2.f; fl += 1.f; ++r;
                }
            }
            // ---- B = V split (trunc hi via PRMT), [pt][ch] SW128 ----
            const int vp = tid >> 3, cseg = (tid & 7) * 8;
            const float4* vsrc =
                (const float4*)&values[((size_t)b * NPTS + n0 + c * 64 + vp) * CIN + cseg];
#pragma unroll
            for (int q = 0; q < 2; ++q) {
                float4 v = vsrc[q];
                const uint32_t bx = __float_as_uint(v.x), by = __float_as_uint(v.y);
                const uint32_t bz = __float_as_uint(v.z), bw = __float_as_uint(v.w);
                const int ch = cseg + q * 4;
                const int o0 = SWZ(vp * 128 + ch * 2);
                const int o1 = SWZ(vp * 128 + (ch + 2) * 2);
                *(uint32_t*)(Bh + o0) = prmt7632(bx, by);
                *(uint32_t*)(Bh + o1) = prmt7632(bz, bw);
                *(uint32_t*)(Bl + o0) = pack_bf2(trunc_res(v.x, bx), trunc_res(v.y, by));
                *(uint32_t*)(Bl + o1) = pack_bf2(trunc_res(v.z, bz), trunc_res(v.w, bw));
            }
        }
        __syncthreads();

        // ---- warp MMA: warp owns rows 16*warp..+15 x all 64 ch ----
        const int rowb = warp * 16;
#pragma unroll
        for (int kk = 0; kk < 4; ++kk) {
            uint32_t ah[4], al[4];
            const int aoff = SWZ((rowb + (lane & 15)) * 128 +
                                 (kk * 16 + 8 * (lane >> 4)) * 2);
            ldsm4(ah, AhU + aoff);
            ldsm4(al, AlU + aoff);
#pragma unroll
            for (int ntp = 0; ntp < 4; ++ntp) {
                uint32_t bh[4], bl[4];
                const int boff = SWZ((kk * 16 + 8 * ((lane >> 3) & 1) + (lane & 7)) * 128 +
                                     (ntp * 16 + 8 * (lane >> 4)) * 2);
                ldsm4t(bh, BhU + boff);
                ldsm4t(bl, BlU + boff);
                mma16816(acc[2 * ntp],     ah, bh);
                mma16816(acc[2 * ntp],     ah, bl);
                mma16816(acc[2 * ntp],     al, bh);
                mma16816(acc[2 * ntp + 1], ah, bh + 2);
                mma16816(acc[2 * ntp + 1], ah, bl + 2);
                mma16816(acc[2 * ntp + 1], al, bh + 2);
            }
        }
    }

    // ---- epilogue: shfl-pair -> float4 atomics ----
    const int row = warp * 16 + (lane >> 2);
#pragma unroll
    for (int nt = 0; nt < 8; ++nt) {
        float* a = acc[nt];
        float o0 = __shfl_down_sync(0xffffffffu, a[0], 1);
        float o1 = __shfl_down_sync(0xffffffffu, a[1], 1);
        float o2 = __shfl_down_sync(0xffffffffu, a[2], 1);
        float o3 = __shfl_down_sync(0xffffffffu, a[3], 1);
        if ((lane & 1) == 0) {
            const int col = nt * 8 + (lane & 2) * 2;     // 0 or 4
            atomicAdd((float4*)&g_S[b][row][col], make_float4(a[0], a[1], o0, o1));
            atomicAdd((float4*)&g_S[b][row + 8][col], make_float4(a[2], a[3], o2, o3));
        }
    }
}

// ---------------- kernel 2: middle (also re-zeroes g_S for next pass) ----------------
__global__ __launch_bounds__(64)
void middle_kernel(const float* __restrict__ W)
{
    const int b = blockIdx.y;
    const int r = blockIdx.x;
    const int d = threadIdx.x;

    int m = 0, base = 0;
    while (base + (L1V - m) <= r) { base += L1V - m; ++m; }
    const int l = m + (r - base);

    double pre  = 2.0 * M_PI * sqrt(4.0 * M_PI / (2.0 * l + 1.0));
    double sph2 = (2.0 * l + 1.0) / (4.0 * M_PI);
    for (int k = l - m + 1; k <= l + m; ++k) sph2 /= (double)k;
    const float clm = (float)(pre * sph2);

    __shared__ float Sc[CIN], Ss[CIN];
    Sc[d] = g_S[b][2 * r][d];
    Ss[d] = g_S[b][2 * r + 1][d];
    g_S[b][2 * r][d]     = 0.f;       // same thread read+zero; rows owned by this block
    g_S[b][2 * r + 1][d] = 0.f;
    __syncthreads();

    float are = 0.f, aim = 0.f;
    const float* Wl = W + l * CIN * COUT;
#pragma unroll 8
    for (int c = 0; c < CIN; ++c) {
        float w = Wl[c * COUT + d];
        are += Sc[c] * w;
        aim += Ss[c] * w;
    }
    are *=  clm;
    aim *= -clm;
    float rre = are > 0.f ? are : SLOPE * are;
    float rim = aim > 0.f ? aim : SLOPE * aim;
    const float fac = (m == 0) ? 1.f : 2.f;
    const float Tc =  fac * rre;
    const float Ts = -fac * rim;

    __nv_bfloat16 hc, lc, hs, ls;
    split_bf(Tc, hc, lc);
    split_bf(Ts, hs, ls);
    g_Tt[b][0][2 * r][d]     = *(uint16_t*)&hc;
    g_Tt[b][0][2 * r + 1][d] = *(uint16_t*)&hs;
    g_Tt[b][1][2 * r][d]     = *(uint16_t*)&lc;
    g_Tt[b][1][2 * r + 1][d] = *(uint16_t*)&ls;
}

// ---------------- kernel 3: synthesis (byte-exact R9 measured-best body) ----------
// out[pt][ch] = sum_k G[pt][k] * T[k][ch].  CTA: 128 pts, 512 threads (16 warps).
// Warp (ptile = w>>1 in 0..7) x (nhalf = w&1).  Double-buffered A/B, one barrier
// per chunk; gen batches 4 steps into conflict-free STS.128.
#define SY_BUF 49152       // per-buffer: Ah 16384 | Al 16384 | Bh 8192 | Bl 8192

__global__ __launch_bounds__(512, 2)
void synthesis_kernel(const float* __restrict__ theta, const float* __restrict__ phi,
                      float* __restrict__ out)
{
    extern __shared__ __align__(1024) char sh[];
    const int tid  = threadIdx.x;
    const int b    = blockIdx.y;
    const int n0   = blockIdx.x * 128;
    const int warp = tid >> 5, lane = tid & 31;
    const int ptile = warp >> 1, nhalf = warp & 1;

    // generator state (threads 0-127; thread = point)
    float x = 0.f, s = 0.f, sphi = 0.f, cphi = 0.f;
    float cm = 1.f, sm = 0.f, pmm = 1.f;
    float pa = 0.f, pb = 1.f, f2 = 1.f, fl = 0.f;
    int m = 0, l = 0, r = 0;
    if (tid < 128) {
        const int n = n0 + tid;
        const float th = theta[b * NPTS + n];
        const float ph = phi[b * NPTS + n];
        x = cosf(th);
        s = sqrtf(fmaxf(1.f - x * x, 0.f));
        sincosf(ph, &sphi, &cphi);
    }

    // emit 32 (cos,sin) k-pairs, batched 4 steps -> 1 STS.128 per split
    auto emit32 = [&](char* base) {
        char* AhD = base;
        char* AlD = base + 16384;
#pragma unroll
        for (int g8 = 0; g8 < 8; ++g8) {
            uint32_t vh[4], vl[4];
#pragma unroll
            for (int q = 0; q < 4; ++q) {
                if (r < NLM) {
                    const float gc = pb * cm, gs = pb * sm;
                    __nv_bfloat16 chh, cll, shh, sll;
                    split_bf(gc, chh, cll);
                    split_bf(gs, shh, sll);
                    vh[q] = pack_bf2(__bfloat162float(chh), __bfloat162float(shh));
                    vl[q] = pack_bf2(__bfloat162float(cll), __bfloat162float(sll));
                    const float pn = (f2 * x * pb - fl * pa) * c_inv[l + 1 - m];
                    pa = pb; pb = pn; f2 += 2.f; fl += 1.f; ++l; ++r;
                    if (l == L1V) {
                        pmm = -(2.f * m + 1.f) * s * pmm;
                        ++m; l = m;
                        const float cn = cm * cphi - sm * sphi;
                        sm = sm * cphi + cm * sphi; cm = cn;
                        pa = 0.f; pb = pmm;
                        f2 = 2.f * m + 1.f; fl = 2.f * m;
                    }
                } else { vh[q] = 0u; vl[q] = 0u; }
            }
            const int off = SWZ(tid * 128 + g8 * 16);
            *(uint4*)(AhD + off) = make_uint4(vh[0], vh[1], vh[2], vh[3]);
            *(uint4*)(AlD + off) = make_uint4(vl[0], vl[1], vl[2], vl[3]);
        }
    };
    // copy B chunk t: threads 128-383, 4 uint4 each
    auto copyB = [&](char* base, int t) {
        const int loc = tid - 128;            // 0..255
        const int sp = loc >> 7;              // 0 hi, 1 lo
        const int kr = (loc >> 1) & 63;
        const int hf = loc & 1;
        const uint4* src = (const uint4*)&g_Tt[b][sp][t * 64 + kr][0];
        char* dst = base + 32768 + sp * 8192;
#pragma unroll
        for (int q = 0; q < 4; ++q)
            *(uint4*)(dst + SWZ(kr * 128 + (hf * 4 + q) * 16)) = src[hf * 4 + q];
    };

    float acc[4][4];
#pragma unroll
    for (int j = 0; j < 4; ++j)
#pragma unroll
        for (int q = 0; q < 4; ++q) acc[j][q] = 0.f;

    if (tid < 128) emit32(sh);
    else if (tid < 384) copyB(sh, 0);
    __syncthreads();

    for (int t = 0; t < 5; ++t) {
        char* buf = sh + (t & 1) * SY_BUF;
        char* nxt = sh + ((t + 1) & 1) * SY_BUF;
        if (t < 4) {
            if (tid < 128) emit32(nxt);
            else if (tid < 384) copyB(nxt, t + 1);
        }

        const uint32_t AhU = smem_u32(buf);
        const uint32_t AlU = AhU + 16384;
        const uint32_t BhU = AhU + 32768;
        const uint32_t BlU = AhU + 40960;
        const int ptb = ptile * 16;
#pragma unroll
        for (int kk = 0; kk < 4; ++kk) {
            uint32_t ah[4], al[4];
            const int aoff = SWZ((ptb + (lane & 15)) * 128 +
                                 (kk * 16 + 8 * (lane >> 4)) * 2);
            ldsm4(ah, AhU + aoff);
            ldsm4(al, AlU + aoff);
#pragma unroll
            for (int j = 0; j < 2; ++j) {
                const int ntp = 2 * nhalf + j;
                uint32_t bh[4], bl[4];
                const int boff = SWZ((kk * 16 + 8 * ((lane >> 3) & 1) + (lane & 7)) * 128 +
                                     (ntp * 16 + 8 * (lane >> 4)) * 2);
                ldsm4t(bh, BhU + boff);
                ldsm4t(bl, BlU + boff);
                mma16816(acc[2 * j],     ah, bh);
                mma16816(acc[2 * j],     ah, bl);
                mma16816(acc[2 * j],     al, bh);
                mma16816(acc[2 * j + 1], ah, bh + 2);
                mma16816(acc[2 * j + 1], ah, bl + 2);
                mma16816(acc[2 * j + 1], al, bh + 2);
            }
        }
        __syncthreads();
    }

    // ---- epilogue: write D fragments ----
    const int g = lane >> 2, t4 = lane & 3;
    float* o0 = &out[((size_t)b * NPTS + n0 + ptile * 16 + g) * COUT];
    float* o1 = &out[((size_t)b * NPTS + n0 + ptile * 16 + g + 8) * COUT];
#pragma unroll
    for (int q = 0; q < 4; ++q) {
        const int col = (2 * nhalf + (q >> 1)) * 16 + (q & 1) * 8 + 2 * t4;
        *(float2*)&o0[col] = make_float2(acc[q][0], acc[q][1]);
        *(float2*)&o1[col] = make_float2(acc[q][2], acc[q][3]);
    }
}

// ---------------- launch ----------------
extern "C" void kernel_launch(void* const* d_in, const int* in_sizes, int n_in,
                              void* d_out, int out_size)
{
    const float* theta  = (const float*)d_in[0];
    const float* phi    = (const float*)d_in[1];
    const float* areas  = (const float*)d_in[2];
    const float* values = (const float*)d_in[3];
    const float* W      = (const float*)d_in[4];
    float* out = (float*)d_out;

    const int an_smem = 86016;
    const int sy_smem = 2 * SY_BUF;     // 98304
    cudaFuncSetAttribute(analysis_kernel,
                         cudaFuncAttributeMaxDynamicSharedMemorySize, an_smem);
    cudaFuncSetAttribute(synthesis_kernel,
                         cudaFuncAttributeMaxDynamicSharedMemorySize, sy_smem);

    analysis_kernel<<<dim3(NPTS / 128, BB), 544, an_smem>>>(theta, phi, areas, values);
    middle_kernel<<<dim3(NLM, BB), 64>>>(W);
    synthesis_kernel<<<dim3(NPTS / 128, BB), 512, sy_smem>>>(theta, phi, out);
}